// round 9
// baseline (speedup 1.0000x reference)
#include <cuda_runtime.h>
#include <cuda_fp16.h>
#include <cstdint>
#include <math.h>

#define NB    4
#define CCH   512
#define HW    4096
#define NGRP  32
#define CPG   16
#define D3    1536
#define SEQ   4096
#define BM    128
#define BN    128
#define BK    32
#define HWC2  (HW * CCH / 2)

/* ---------------- scratch ---------------- */
__device__ uint32_t g_sh[(size_t)NB * HWC2];
__device__ uint32_t g_sl[(size_t)NB * HWC2];
__device__ uint32_t g_wi[(size_t)D3 * CCH / 2];
__device__ uint32_t g_wo[(size_t)CCH * CCH / 2];
__device__ uint32_t g_qh[(size_t)NB * HWC2];
__device__ uint32_t g_ql[(size_t)NB * HWC2];
__device__ uint32_t g_k [(size_t)NB * HWC2];
__device__ uint32_t g_v [(size_t)NB * HWC2];
__device__ uint32_t g_ph[(size_t)NB * SEQ * SEQ / 2];    /* exp'd P fp16 */
__device__ float    g_pm[(size_t)NB * SEQ * 32];         /* [z][s][tile] m  */
__device__ float    g_ps[(size_t)NB * SEQ * 32];         /* [z][s][tile] sum */
__device__ float    g_f [(size_t)NB * SEQ * 32];         /* [z][s][tile] corr */
__device__ uint32_t g_ah[(size_t)NB * HWC2];
__device__ uint32_t g_al[(size_t)NB * HWC2];

/* ---------------- helpers ---------------- */
__device__ __forceinline__ uint32_t smem_u32(const void* p) {
    uint32_t a;
    asm("{ .reg .u64 t; cvta.to.shared.u64 t, %1; cvt.u32.u64 %0, t; }"
        : "=r"(a) : "l"(p));
    return a;
}
__device__ __forceinline__ uint32_t cvtf16x2(float hi, float lo) {
    uint32_t d;
    asm("cvt.rn.f16x2.f32 %0, %1, %2;" : "=r"(d) : "f"(hi), "f"(lo));
    return d;
}
__device__ __forceinline__ float2 unpack_h2(uint32_t u) {
    __half2 h = *reinterpret_cast<__half2*>(&u);
    return make_float2(__low2float(h), __high2float(h));
}
__device__ __forceinline__ void split_pair(float v0, float v1,
                                           uint32_t& hp, uint32_t& lp) {
    hp = cvtf16x2(v1, v0);
    float2 h = unpack_h2(hp);
    lp = cvtf16x2(v1 - h.y, v0 - h.x);
}
__device__ __forceinline__ void cpa16(uint32_t dst, const void* src) {
    asm volatile("cp.async.cg.shared.global [%0], [%1], 16;"
                 :: "r"(dst), "l"(src) : "memory");
}
__device__ __forceinline__ void ldsm4(uint32_t* r, uint32_t addr) {
    asm volatile("ldmatrix.sync.aligned.m8n8.x4.shared.b16 {%0,%1,%2,%3}, [%4];"
        : "=r"(r[0]), "=r"(r[1]), "=r"(r[2]), "=r"(r[3]) : "r"(addr));
}
__device__ __forceinline__ void ldsm2(uint32_t* r, uint32_t addr) {
    asm volatile("ldmatrix.sync.aligned.m8n8.x2.shared.b16 {%0,%1}, [%2];"
        : "=r"(r[0]), "=r"(r[1]) : "r"(addr));
}
__device__ __forceinline__ void ldsm2t(uint32_t* r, uint32_t addr) {
    asm volatile("ldmatrix.sync.aligned.m8n8.x2.trans.shared.b16 {%0,%1}, [%2];"
        : "=r"(r[0]), "=r"(r[1]) : "r"(addr));
}
__device__ __forceinline__ void mmaf16(float* c, const uint32_t* a, const uint32_t* b) {
    asm volatile("mma.sync.aligned.m16n8k16.row.col.f32.f16.f16.f32 "
        "{%0,%1,%2,%3}, {%4,%5,%6,%7}, {%8,%9}, {%0,%1,%2,%3};"
        : "+f"(c[0]), "+f"(c[1]), "+f"(c[2]), "+f"(c[3])
        : "r"(a[0]), "r"(a[1]), "r"(a[2]), "r"(a[3]), "r"(b[0]), "r"(b[1]));
}
__device__ __forceinline__ void mulh2(uint32_t& a, uint32_t f) {
    asm("mul.rn.f16x2 %0, %0, %1;" : "+r"(a) : "r"(f));
}

#define ASZ 10240                       /* 128 rows x 80B */
#define BSZT (32 * 272)                 /* trans-B tile: 32 rows x 272B */

/* ======== fp16 GEMM, 3-stage cp.async, 2 CTA/SM ========
 * C[M,N] = (Ah(+Al))[M,K] . B[N,K]^T
 * MODE 0: QKV (+bias, split-q/k/v routing)
 * MODE 1: scores -> exp'd fp16 P + per-tile (max,sum) partials
 * MODE 2: PV with per-tile correction factors f (A-frag f16x2 multiply)
 * MODE 3: proj (+b_out +x residual, transposed store)
 */
template <int MODE, bool TB, bool SPLITA>
__global__ __launch_bounds__(256, 2)
void gemm_f16(const uint32_t* __restrict__ Ah, const uint32_t* __restrict__ Al,
              const uint32_t* __restrict__ Bg,
              void* __restrict__ o0, void* __restrict__ o1,
              void* __restrict__ o2, void* __restrict__ o3,
              const float* __restrict__ bias, const float* __restrict__ resid,
              int K, int ldaB, int ldbB, int ldc,
              size_t AzS, size_t BzS, size_t CzS)
{
    extern __shared__ char sm[];
    const uint32_t sb = smem_u32(sm);
    const int t = threadIdx.x, wid = t >> 5, lid = t & 31;
    const int wm = wid >> 2, wn = wid & 3;
    const int m0 = blockIdx.y * BM, n0 = blockIdx.x * BN, z = blockIdx.z;

    const int NA  = SPLITA ? 2 : 1;
    const int BSZ = TB ? BSZT : ASZ;
    const int STG = NA * ASZ + BSZ;

    const char* Ahp = (const char*)(Ah + z * AzS);
    const char* Alp = SPLITA ? (const char*)(Al + z * AzS) : nullptr;
    const char* Bp  = (const char*)(Bg + z * BzS);

    /* PV: preload this CTA's f block [128 rows x 32 tiles] into smem */
    float* fs = (float*)(sm + 3 * STG);
    if (MODE == 2) {
        const float* Fg = g_f + ((size_t)z * SEQ + m0) * 32;
        for (int i = t; i < 128 * 32; i += 256) fs[i] = Fg[i];
    }

    float acc[4][4][4];
#pragma unroll
    for (int a = 0; a < 4; a++)
#pragma unroll
        for (int b = 0; b < 4; b++)
#pragma unroll
            for (int q = 0; q < 4; q++) acc[a][b][q] = 0.f;

    auto load_stage = [&](int i, int buf) {
        uint32_t d = sb + (uint32_t)buf * STG;
#pragma unroll
        for (int rep = 0; rep < 2; rep++) {
            int cid = rep * 256 + t;
            int row = cid >> 2, ch = cid & 3;
            size_t ao = (size_t)(m0 + row) * ldaB + (size_t)i * 64 + ch * 16;
            cpa16(d + row * 80 + ch * 16, Ahp + ao);
            if (SPLITA)
                cpa16(d + ASZ + row * 80 + ch * 16, Alp + ao);
            if (!TB) {
                cpa16(d + NA * ASZ + row * 80 + ch * 16,
                      Bp + (size_t)(n0 + row) * ldbB + (size_t)i * 64 + ch * 16);
            } else {
                int br = cid >> 4, bc = cid & 15;
                cpa16(d + NA * ASZ + br * 272 + bc * 16,
                      Bp + (size_t)(i * 32 + br) * ldbB + (size_t)n0 * 2 + bc * 16);
            }
        }
        asm volatile("cp.async.commit_group;" ::: "memory");
    };

    const int nch = K / BK;
    load_stage(0, 0);
    if (nch > 1) load_stage(1, 1);

    uint32_t fh0[4], fh1[4];
    int buf = 0;
    for (int i = 0; i < nch; i++) {
        if (i + 1 < nch)
            asm volatile("cp.async.wait_group 1;" ::: "memory");
        else
            asm volatile("cp.async.wait_group 0;" ::: "memory");
        __syncthreads();
        if (i + 2 < nch) {
            int nb = buf + 2; if (nb >= 3) nb -= 3;
            load_stage(i + 2, nb);
        }
        if (MODE == 2 && (i & 3) == 0) {
            int kt = i >> 2;
#pragma unroll
            for (int mt = 0; mt < 4; mt++) {
                int rl = wm * 64 + mt * 16 + (lid >> 2);
                float f0 = fs[rl * 32 + kt];
                float f1 = fs[(rl + 8) * 32 + kt];
                fh0[mt] = cvtf16x2(f0, f0);
                fh1[mt] = cvtf16x2(f1, f1);
            }
        }
        const uint32_t bb = sb + (uint32_t)buf * STG;
#pragma unroll
        for (int ks = 0; ks < 2; ks++) {
            uint32_t ah[4][4], al[4][4], bf[4][2];
#pragma unroll
            for (int mt = 0; mt < 4; mt++) {
                uint32_t r = (uint32_t)(wm * 64 + mt * 16 + (lid & 15));
                uint32_t off = r * 80 + (uint32_t)((ks * 2 + (lid >> 4)) * 16);
                ldsm4(ah[mt], bb + off);
                if (SPLITA) ldsm4(al[mt], bb + ASZ + off);
                if (MODE == 2) {
                    mulh2(ah[mt][0], fh0[mt]); mulh2(ah[mt][2], fh0[mt]);
                    mulh2(ah[mt][1], fh1[mt]); mulh2(ah[mt][3], fh1[mt]);
                }
            }
#pragma unroll
            for (int nt = 0; nt < 4; nt++) {
                if (!TB) {
                    uint32_t r = (uint32_t)(wn * 32 + nt * 8 + (lid & 7));
                    uint32_t off = r * 80 + (uint32_t)((ks * 2 + ((lid >> 3) & 1)) * 16);
                    ldsm2(bf[nt], bb + NA * ASZ + off);
                } else {
                    uint32_t r = (uint32_t)(ks * 16 + (lid & 15));
                    uint32_t off = r * 272 + (uint32_t)((wn * 32 + nt * 8) * 2);
                    ldsm2t(bf[nt], bb + NA * ASZ + off);
                }
            }
#pragma unroll
            for (int mt = 0; mt < 4; mt++)
#pragma unroll
                for (int nt = 0; nt < 4; nt++) {
                    mmaf16(acc[mt][nt], ah[mt], bf[nt]);
                    if (SPLITA) mmaf16(acc[mt][nt], al[mt], bf[nt]);
                }
        }
        buf++; if (buf == 3) buf = 0;
    }
    __syncthreads();

    /* ---------------- epilogues ---------------- */
    if (MODE == 1) {               /* scores -> exp'd fp16 P + partials */
        float* stg = (float*)sm;
        float* smx = (float*)(sm + 67584);
        float* ssm = smx + 256;
        const float S = 0.044194173824159216f;
#pragma unroll
        for (int mt = 0; mt < 4; mt++)
#pragma unroll
            for (int nt = 0; nt < 4; nt++) {
                int r0 = wm * 64 + mt * 16 + (lid >> 2);
                int c0 = wn * 32 + nt * 8 + 2 * (lid & 3);
                *(float2*)&stg[r0 * 132 + c0] =
                    make_float2(acc[mt][nt][0] * S, acc[mt][nt][1] * S);
                *(float2*)&stg[(r0 + 8) * 132 + c0] =
                    make_float2(acc[mt][nt][2] * S, acc[mt][nt][3] * S);
            }
        __syncthreads();
        const int row = t >> 1, half = t & 1;
        const float* rp = stg + row * 132 + half * 64;
        float mx = -1e30f;
#pragma unroll
        for (int j = 0; j < 16; j++) {
            float4 v = *(const float4*)(rp + j * 4);
            mx = fmaxf(mx, fmaxf(fmaxf(v.x, v.y), fmaxf(v.z, v.w)));
        }
        smx[t] = mx;
        __syncthreads();
        const float mt_ = fmaxf(smx[row * 2], smx[row * 2 + 1]);
        float sum = 0.f;
        uint2* php = (uint2*)((uint32_t*)o0 + z * CzS +
                     (size_t)(m0 + row) * 2048 + (n0 >> 1) + half * 32);
#pragma unroll
        for (int j = 0; j < 16; j++) {
            float4 v = *(const float4*)(rp + j * 4);
            float e0 = __expf(v.x - mt_), e1 = __expf(v.y - mt_);
            float e2 = __expf(v.z - mt_), e3 = __expf(v.w - mt_);
            sum += (e0 + e1) + (e2 + e3);
            php[j] = make_uint2(cvtf16x2(e1, e0), cvtf16x2(e3, e2));
        }
        ssm[t] = sum;
        __syncthreads();
        if (t < 128) {
            size_t pb = ((size_t)z * SEQ + m0 + t) * 32 + blockIdx.x;
            g_pm[pb] = fmaxf(smx[t * 2], smx[t * 2 + 1]);
            g_ps[pb] = ssm[t * 2] + ssm[t * 2 + 1];
        }
    } else if (MODE == 3) {
        float* stg = (float*)sm;
#pragma unroll
        for (int mt = 0; mt < 4; mt++)
#pragma unroll
            for (int nt = 0; nt < 4; nt++) {
                int r0 = wm * 64 + mt * 16 + (lid >> 2);
                int c0 = wn * 32 + nt * 8 + 2 * (lid & 3);
                stg[r0 * 129 + c0]           = acc[mt][nt][0];
                stg[r0 * 129 + c0 + 1]       = acc[mt][nt][1];
                stg[(r0 + 8) * 129 + c0]     = acc[mt][nt][2];
                stg[(r0 + 8) * 129 + c0 + 1] = acc[mt][nt][3];
            }
        __syncthreads();
        float* op = (float*)o0 + z * CzS;
        const float* xp = resid + z * CzS;
#pragma unroll 8
        for (int p = 0; p < 64; p++) {
            int r = p * 2 + (t >> 7);
            int s = t & 127;
            int c = n0 + r;
            op[(size_t)c * HW + m0 + s] =
                stg[s * 129 + r] + bias[c] + xp[(size_t)c * HW + m0 + s];
        }
    } else {                       /* MODE 0 QKV / MODE 2 PV fp16 writes */
        uint32_t* stg = (uint32_t*)sm;
        uint32_t *dh, *dl = nullptr;
        int cb;
        bool split;
        if (MODE == 0) {
            if (n0 < 512)      { dh = (uint32_t*)o0 + (size_t)z * HWC2;
                                 dl = (uint32_t*)o1 + (size_t)z * HWC2;
                                 cb = n0 >> 1; split = true; }
            else if (n0 < 1024){ dh = (uint32_t*)o2 + (size_t)z * HWC2;
                                 cb = (n0 - 512) >> 1; split = false; }
            else               { dh = (uint32_t*)o3 + (size_t)z * HWC2;
                                 cb = (n0 - 1024) >> 1; split = false; }
        } else {
            dh = (uint32_t*)o0 + (size_t)z * HWC2;
            dl = (uint32_t*)o1 + (size_t)z * HWC2;
            cb = n0 >> 1; split = true;
        }
        float bb0[4], bb1[4];
#pragma unroll
        for (int nt = 0; nt < 4; nt++) {
            if (MODE == 0) {
                int c0 = wn * 32 + nt * 8 + 2 * (lid & 3);
                bb0[nt] = bias[n0 + c0];
                bb1[nt] = bias[n0 + c0 + 1];
            } else { bb0[nt] = 0.f; bb1[nt] = 0.f; }
        }
        for (int pass = 0; pass < (split ? 2 : 1); pass++) {
#pragma unroll
            for (int mt = 0; mt < 4; mt++)
#pragma unroll
                for (int nt = 0; nt < 4; nt++) {
                    int r0 = wm * 64 + mt * 16 + (lid >> 2);
                    int cu = ((wn * 32 + nt * 8) >> 1) + (lid & 3);
                    uint32_t hp, lp;
                    split_pair(acc[mt][nt][0] + bb0[nt], acc[mt][nt][1] + bb1[nt], hp, lp);
                    stg[r0 * 68 + cu] = pass ? lp : hp;
                    split_pair(acc[mt][nt][2] + bb0[nt], acc[mt][nt][3] + bb1[nt], hp, lp);
                    stg[(r0 + 8) * 68 + cu] = pass ? lp : hp;
                }
            __syncthreads();
            uint32_t* dst = pass ? dl : dh;
            int r = t >> 1, hb = (t & 1) * 32;
#pragma unroll
            for (int q2 = 0; q2 < 8; q2++) {
                uint4 v = *(uint4*)&stg[r * 68 + hb + q2 * 4];
                *(uint4*)&dst[(size_t)(m0 + r) * 256 + cb + hb + q2 * 4] = v;
            }
            __syncthreads();
        }
    }
}

/* ================== reduce partials -> correction factors ================== */
__global__ __launch_bounds__(256) void reduce_f()
{
    const int w = threadIdx.x >> 5, lane = threadIdx.x & 31;
    const size_t row = (size_t)blockIdx.x * 8 + w;
    const float m_i = g_pm[row * 32 + lane];
    const float s_i = g_ps[row * 32 + lane];
    float m = m_i;
#pragma unroll
    for (int o = 16; o > 0; o >>= 1)
        m = fmaxf(m, __shfl_xor_sync(0xFFFFFFFFu, m, o));
    const float e = __expf(m_i - m);
    float l = s_i * e;
#pragma unroll
    for (int o = 16; o > 0; o >>= 1)
        l += __shfl_xor_sync(0xFFFFFFFFu, l, o);
    g_f[row * 32 + lane] = e / l;
}

/* ================== GroupNorm -> split fp16 seq ================== */
__global__ __launch_bounds__(256) void gn_kernel(
    const float* __restrict__ x,
    const float* __restrict__ gamma,
    const float* __restrict__ beta)
{
    __shared__ float rs[256], rss[256];
    __shared__ float tile[16 * 257];
    __shared__ float sc[16], sh[16];
    const int g = blockIdx.x, n = g >> 5, grp = g & 31;
    const float* xp = x + ((size_t)n * CCH + (size_t)grp * CPG) * HW;
    uint32_t* oh = g_sh + (size_t)n * HWC2;
    uint32_t* ol = g_sl + (size_t)n * HWC2;
    const int NE = CPG * HW;

    float s = 0.f, ss = 0.f;
    for (int i = threadIdx.x; i < NE; i += 256) {
        float v = xp[i];
        s += v; ss += v * v;
    }
    rs[threadIdx.x] = s; rss[threadIdx.x] = ss;
    __syncthreads();
    for (int o = 128; o > 0; o >>= 1) {
        if (threadIdx.x < o) {
            rs[threadIdx.x] += rs[threadIdx.x + o];
            rss[threadIdx.x] += rss[threadIdx.x + o];
        }
        __syncthreads();
    }
    const float mean = rs[0] * (1.0f / NE);
    const float var  = rss[0] * (1.0f / NE) - mean * mean;
    const float rstd = rsqrtf(var + 1e-5f);
    if (threadIdx.x < 16) {
        int ch = grp * 16 + threadIdx.x;
        float gm = gamma[ch];
        sc[threadIdx.x] = rstd * gm;
        sh[threadIdx.x] = beta[ch] - mean * rstd * gm;
    }
    __syncthreads();

    for (int s0 = 0; s0 < HW; s0 += 256) {
#pragma unroll
        for (int ch = 0; ch < 16; ch++)
            tile[ch * 257 + threadIdx.x] = xp[(size_t)ch * HW + s0 + threadIdx.x] * sc[ch] + sh[ch];
        __syncthreads();
        size_t rowb = (size_t)(s0 + threadIdx.x) * 256 + grp * 8;
#pragma unroll
        for (int c4 = 0; c4 < 4; c4++) {
            float v0 = tile[(c4 * 4 + 0) * 257 + threadIdx.x];
            float v1 = tile[(c4 * 4 + 1) * 257 + threadIdx.x];
            float v2 = tile[(c4 * 4 + 2) * 257 + threadIdx.x];
            float v3 = tile[(c4 * 4 + 3) * 257 + threadIdx.x];
            uint32_t h0, l0, h1, l1;
            split_pair(v0, v1, h0, l0);
            split_pair(v2, v3, h1, l1);
            oh[rowb + c4 * 2]     = h0;
            oh[rowb + c4 * 2 + 1] = h1;
            ol[rowb + c4 * 2]     = l0;
            ol[rowb + c4 * 2 + 1] = l1;
        }
        __syncthreads();
    }
}

/* ================== round weights to fp16 ================== */
__global__ __launch_bounds__(256) void round_w(
    const float* __restrict__ src, uint32_t* __restrict__ dst, int npairs)
{
    int i = blockIdx.x * 256 + threadIdx.x;
    if (i < npairs) {
        float2 v = *(const float2*)&src[2 * i];
        dst[i] = cvtf16x2(v.y, v.x);
    }
}

/* ================== launch ================== */
extern "C" void kernel_launch(void* const* d_in, const int* in_sizes, int n_in,
                              void* d_out, int out_size)
{
    const float* x     = (const float*)d_in[0];
    const float* gns   = (const float*)d_in[1];
    const float* gnb   = (const float*)d_in[2];
    const float* w_in  = (const float*)d_in[3];
    const float* b_in  = (const float*)d_in[4];
    const float* w_out = (const float*)d_in[5];
    const float* b_out = (const float*)d_in[6];
    float* out = (float*)d_out;

    uint32_t *sh, *sl, *wi, *wo, *qh, *ql, *kk, *vv, *ph, *ath, *atl;
    cudaGetSymbolAddress((void**)&sh,  g_sh);
    cudaGetSymbolAddress((void**)&sl,  g_sl);
    cudaGetSymbolAddress((void**)&wi,  g_wi);
    cudaGetSymbolAddress((void**)&wo,  g_wo);
    cudaGetSymbolAddress((void**)&qh,  g_qh);
    cudaGetSymbolAddress((void**)&ql,  g_ql);
    cudaGetSymbolAddress((void**)&kk,  g_k);
    cudaGetSymbolAddress((void**)&vv,  g_v);
    cudaGetSymbolAddress((void**)&ph,  g_ph);
    cudaGetSymbolAddress((void**)&ath, g_ah);
    cudaGetSymbolAddress((void**)&atl, g_al);

    const int SM_SPLIT = 3 * (3 * ASZ);                  /* 92160 */
    const int SM_PV    = 3 * (ASZ + BSZT) + 128 * 32 * 4; /* 73216 */

    cudaFuncSetAttribute(gemm_f16<0, false, true >, cudaFuncAttributeMaxDynamicSharedMemorySize, SM_SPLIT);
    cudaFuncSetAttribute(gemm_f16<1, false, true >, cudaFuncAttributeMaxDynamicSharedMemorySize, SM_SPLIT);
    cudaFuncSetAttribute(gemm_f16<2, true,  false>, cudaFuncAttributeMaxDynamicSharedMemorySize, SM_PV);
    cudaFuncSetAttribute(gemm_f16<3, false, true >, cudaFuncAttributeMaxDynamicSharedMemorySize, SM_SPLIT);

    gn_kernel<<<NB * NGRP, 256>>>(x, gns, gnb);
    round_w<<<(D3 * CCH / 2 + 255) / 256, 256>>>(w_in, wi, D3 * CCH / 2);
    round_w<<<(CCH * CCH / 2 + 255) / 256, 256>>>(w_out, wo, CCH * CCH / 2);

    /* QKV */
    gemm_f16<0, false, true><<<dim3(D3 / BN, HW / BM, NB), 256, SM_SPLIT>>>(
        sh, sl, wi, qh, ql, kk, vv, b_in, nullptr,
        CCH, CCH * 2, CCH * 2, 0, HWC2, 0, 0);

    /* scores -> exp'd fp16 P + partials */
    gemm_f16<1, false, true><<<dim3(SEQ / BN, SEQ / BM, NB), 256, SM_SPLIT>>>(
        qh, ql, kk, ph, nullptr, nullptr, nullptr, nullptr, nullptr,
        CCH, CCH * 2, CCH * 2, SEQ, HWC2, HWC2, (size_t)SEQ * SEQ / 2);

    /* combine partials -> f */
    reduce_f<<<NB * SEQ / 8, 256>>>();

    /* att = (P*f) . V */
    gemm_f16<2, true, false><<<dim3(CCH / BN, SEQ / BM, NB), 256, SM_PV>>>(
        ph, nullptr, vv, ath, atl, nullptr, nullptr, nullptr, nullptr,
        SEQ, SEQ * 2, CCH * 2, 0, (size_t)SEQ * SEQ / 2, HWC2, 0);

    /* proj + bias + residual -> d_out */
    gemm_f16<3, false, true><<<dim3(CCH / BN, HW / BM, NB), 256, SM_SPLIT>>>(
        ath, atl, wo, out, nullptr, nullptr, nullptr, b_out, x,
        CCH, CCH * 2, CCH * 2, HW, HWC2, 0, (size_t)CCH * HW);
}

// round 10
// speedup vs baseline: 1.4302x; 1.4302x over previous
#include <cuda_runtime.h>
#include <cuda_fp16.h>
#include <cstdint>
#include <math.h>

#define NB    4
#define CCH   512
#define HW    4096
#define NGRP  32
#define CPG   16
#define D3    1536
#define SEQ   4096
#define BM    128
#define BN    128
#define BK    32
#define HWC2  (HW * CCH / 2)

/* ---------------- scratch (all single fp16 as u32 pairs) ---------------- */
__device__ uint32_t g_s [(size_t)NB * HWC2];          /* GN(x) [s][c]     */
__device__ uint32_t g_wi[(size_t)D3 * CCH / 2];
__device__ uint32_t g_wo[(size_t)CCH * CCH / 2];
__device__ uint32_t g_q [(size_t)NB * HWC2];
__device__ uint32_t g_k [(size_t)NB * HWC2];
__device__ uint32_t g_v [(size_t)NB * HWC2];
__device__ uint32_t g_p [(size_t)NB * SEQ * SEQ / 2]; /* scores -> P in place */
__device__ uint32_t g_at[(size_t)NB * HWC2];

/* ---------------- helpers ---------------- */
__device__ __forceinline__ uint32_t smem_u32(const void* p) {
    uint32_t a;
    asm("{ .reg .u64 t; cvta.to.shared.u64 t, %1; cvt.u32.u64 %0, t; }"
        : "=r"(a) : "l"(p));
    return a;
}
__device__ __forceinline__ uint32_t cvtf16x2(float hi, float lo) {
    uint32_t d;
    asm("cvt.rn.f16x2.f32 %0, %1, %2;" : "=r"(d) : "f"(hi), "f"(lo));
    return d;
}
__device__ __forceinline__ float2 unpack_h2(uint32_t u) {
    __half2 h = *reinterpret_cast<__half2*>(&u);
    return make_float2(__low2float(h), __high2float(h));
}
__device__ __forceinline__ void cpa16(uint32_t dst, const void* src) {
    asm volatile("cp.async.cg.shared.global [%0], [%1], 16;"
                 :: "r"(dst), "l"(src) : "memory");
}
__device__ __forceinline__ void ldsm4(uint32_t* r, uint32_t addr) {
    asm volatile("ldmatrix.sync.aligned.m8n8.x4.shared.b16 {%0,%1,%2,%3}, [%4];"
        : "=r"(r[0]), "=r"(r[1]), "=r"(r[2]), "=r"(r[3]) : "r"(addr));
}
__device__ __forceinline__ void ldsm2(uint32_t* r, uint32_t addr) {
    asm volatile("ldmatrix.sync.aligned.m8n8.x2.shared.b16 {%0,%1}, [%2];"
        : "=r"(r[0]), "=r"(r[1]) : "r"(addr));
}
__device__ __forceinline__ void ldsm2t(uint32_t* r, uint32_t addr) {
    asm volatile("ldmatrix.sync.aligned.m8n8.x2.trans.shared.b16 {%0,%1}, [%2];"
        : "=r"(r[0]), "=r"(r[1]) : "r"(addr));
}
__device__ __forceinline__ void mmaf16(float* c, const uint32_t* a, const uint32_t* b) {
    asm volatile("mma.sync.aligned.m16n8k16.row.col.f32.f16.f16.f32 "
        "{%0,%1,%2,%3}, {%4,%5,%6,%7}, {%8,%9}, {%0,%1,%2,%3};"
        : "+f"(c[0]), "+f"(c[1]), "+f"(c[2]), "+f"(c[3])
        : "r"(a[0]), "r"(a[1]), "r"(a[2]), "r"(a[3]), "r"(b[0]), "r"(b[1]));
}

#define ASZ 10240                       /* 128 rows x 80B */
#define BSZT (32 * 272)                 /* trans-B tile: 32 rows x 272B */

/* ======== single-fp16 GEMM, 3-stage cp.async, 2 CTA/SM ========
 * C[M,N] = A[M,K] . B[N,K]^T (TB: B stored [K,N], loaded via ldmatrix.trans)
 * MODE 0: QKV (+bias, q/k/v routing), fp16 out
 * MODE 1: scores (*1/sqrt(512)), fp16 out (wide ldcu)
 * MODE 2: PV, fp16 out
 * MODE 3: proj (+b_out +x residual, transposed fp32 store)
 */
template <int MODE, bool TB>
__global__ __launch_bounds__(256, 2)
void gemm_f16(const uint32_t* __restrict__ A, const uint32_t* __restrict__ B,
              void* __restrict__ o0, void* __restrict__ o1,
              void* __restrict__ o2,
              const float* __restrict__ bias, const float* __restrict__ resid,
              int K, int ldaB, int ldbB, int ldcu,
              size_t AzS, size_t BzS, size_t CzS)
{
    extern __shared__ char sm[];
    const uint32_t sb = smem_u32(sm);
    const int t = threadIdx.x, wid = t >> 5, lid = t & 31;
    const int wm = wid >> 2, wn = wid & 3;
    const int m0 = blockIdx.y * BM, n0 = blockIdx.x * BN, z = blockIdx.z;

    const int BSZ = TB ? BSZT : ASZ;
    const int STG = ASZ + BSZ;

    const char* Ap = (const char*)(A + z * AzS);
    const char* Bp = (const char*)(B + z * BzS);

    float acc[4][4][4];
#pragma unroll
    for (int a = 0; a < 4; a++)
#pragma unroll
        for (int b = 0; b < 4; b++)
#pragma unroll
            for (int q = 0; q < 4; q++) acc[a][b][q] = 0.f;

    auto load_stage = [&](int i, int buf) {
        uint32_t d = sb + (uint32_t)buf * STG;
#pragma unroll
        for (int rep = 0; rep < 2; rep++) {
            int cid = rep * 256 + t;
            int row = cid >> 2, ch = cid & 3;
            cpa16(d + row * 80 + ch * 16,
                  Ap + (size_t)(m0 + row) * ldaB + (size_t)i * 64 + ch * 16);
            if (!TB) {
                cpa16(d + ASZ + row * 80 + ch * 16,
                      Bp + (size_t)(n0 + row) * ldbB + (size_t)i * 64 + ch * 16);
            } else {
                int br = cid >> 4, bc = cid & 15;
                cpa16(d + ASZ + br * 272 + bc * 16,
                      Bp + (size_t)(i * 32 + br) * ldbB + (size_t)n0 * 2 + bc * 16);
            }
        }
        asm volatile("cp.async.commit_group;" ::: "memory");
    };

    const int nch = K / BK;
    load_stage(0, 0);
    if (nch > 1) load_stage(1, 1);

    int buf = 0;
    for (int i = 0; i < nch; i++) {
        if (i + 1 < nch)
            asm volatile("cp.async.wait_group 1;" ::: "memory");
        else
            asm volatile("cp.async.wait_group 0;" ::: "memory");
        __syncthreads();
        if (i + 2 < nch) {
            int nb = buf + 2; if (nb >= 3) nb -= 3;
            load_stage(i + 2, nb);
        }
        const uint32_t bb = sb + (uint32_t)buf * STG;
#pragma unroll
        for (int ks = 0; ks < 2; ks++) {
            uint32_t ah[4][4], bf[4][2];
#pragma unroll
            for (int mt = 0; mt < 4; mt++) {
                uint32_t r = (uint32_t)(wm * 64 + mt * 16 + (lid & 15));
                uint32_t off = r * 80 + (uint32_t)((ks * 2 + (lid >> 4)) * 16);
                ldsm4(ah[mt], bb + off);
            }
#pragma unroll
            for (int nt = 0; nt < 4; nt++) {
                if (!TB) {
                    uint32_t r = (uint32_t)(wn * 32 + nt * 8 + (lid & 7));
                    uint32_t off = r * 80 + (uint32_t)((ks * 2 + ((lid >> 3) & 1)) * 16);
                    ldsm2(bf[nt], bb + ASZ + off);
                } else {
                    uint32_t r = (uint32_t)(ks * 16 + (lid & 15));
                    uint32_t off = r * 272 + (uint32_t)((wn * 32 + nt * 8) * 2);
                    ldsm2t(bf[nt], bb + ASZ + off);
                }
            }
#pragma unroll
            for (int mt = 0; mt < 4; mt++)
#pragma unroll
                for (int nt = 0; nt < 4; nt++)
                    mmaf16(acc[mt][nt], ah[mt], bf[nt]);
        }
        buf++; if (buf == 3) buf = 0;
    }
    __syncthreads();

    /* ---------------- epilogues ---------------- */
    if (MODE == 3) {              /* proj: transpose + bias + residual, fp32 */
        float* stg = (float*)sm;
#pragma unroll
        for (int mt = 0; mt < 4; mt++)
#pragma unroll
            for (int nt = 0; nt < 4; nt++) {
                int r0 = wm * 64 + mt * 16 + (lid >> 2);
                int c0 = wn * 32 + nt * 8 + 2 * (lid & 3);
                stg[r0 * 129 + c0]           = acc[mt][nt][0];
                stg[r0 * 129 + c0 + 1]       = acc[mt][nt][1];
                stg[(r0 + 8) * 129 + c0]     = acc[mt][nt][2];
                stg[(r0 + 8) * 129 + c0 + 1] = acc[mt][nt][3];
            }
        __syncthreads();
        float* op = (float*)o0 + z * CzS;
        const float* xp = resid + z * CzS;
#pragma unroll 8
        for (int p = 0; p < 64; p++) {
            int r = p * 2 + (t >> 7);
            int s = t & 127;
            int c = n0 + r;
            op[(size_t)c * HW + m0 + s] =
                stg[s * 129 + r] + bias[c] + xp[(size_t)c * HW + m0 + s];
        }
    } else {                      /* fp16 staged coalesced write */
        uint32_t* stg = (uint32_t*)sm;
        uint32_t* dh;
        int cb;
        if (MODE == 0) {
            if (n0 < 512)       { dh = (uint32_t*)o0 + (size_t)z * CzS; cb = n0 >> 1; }
            else if (n0 < 1024) { dh = (uint32_t*)o1 + (size_t)z * CzS; cb = (n0 - 512) >> 1; }
            else                { dh = (uint32_t*)o2 + (size_t)z * CzS; cb = (n0 - 1024) >> 1; }
        } else {
            dh = (uint32_t*)o0 + (size_t)z * CzS;
            cb = n0 >> 1;
        }
        const float S = 0.044194173824159216f;
        float bb0[4], bb1[4];
#pragma unroll
        for (int nt = 0; nt < 4; nt++) {
            if (MODE == 0) {
                int c0 = wn * 32 + nt * 8 + 2 * (lid & 3);
                bb0[nt] = bias[n0 + c0];
                bb1[nt] = bias[n0 + c0 + 1];
            } else { bb0[nt] = 0.f; bb1[nt] = 0.f; }
        }
#pragma unroll
        for (int mt = 0; mt < 4; mt++)
#pragma unroll
            for (int nt = 0; nt < 4; nt++) {
                int r0 = wm * 64 + mt * 16 + (lid >> 2);
                int cu = ((wn * 32 + nt * 8) >> 1) + (lid & 3);
                float v0 = acc[mt][nt][0], v1 = acc[mt][nt][1];
                float v2 = acc[mt][nt][2], v3 = acc[mt][nt][3];
                if (MODE == 1) { v0 *= S; v1 *= S; v2 *= S; v3 *= S; }
                else if (MODE == 0) { v0 += bb0[nt]; v1 += bb1[nt];
                                      v2 += bb0[nt]; v3 += bb1[nt]; }
                stg[r0 * 68 + cu]       = cvtf16x2(v1, v0);
                stg[(r0 + 8) * 68 + cu] = cvtf16x2(v3, v2);
            }
        __syncthreads();
        int r = t >> 1, hb = (t & 1) * 32;
#pragma unroll
        for (int q2 = 0; q2 < 8; q2++) {
            uint4 v = *(uint4*)&stg[r * 68 + hb + q2 * 4];
            *(uint4*)&dh[(size_t)(m0 + r) * ldcu + cb + hb + q2 * 4] = v;
        }
    }
}

/* ================== in-place fp16 softmax over P rows ================== */
__global__ __launch_bounds__(256) void softmax_f16()
{
    uint4* p = (uint4*)(g_p + (size_t)blockIdx.x * 2048);
    __shared__ float red[256];
    const int t = threadIdx.x;

    uint4 d0 = p[t], d1 = p[t + 256];
    float v[16];
    {
        float2 a;
        a = unpack_h2(d0.x); v[0] = a.x; v[1] = a.y;
        a = unpack_h2(d0.y); v[2] = a.x; v[3] = a.y;
        a = unpack_h2(d0.z); v[4] = a.x; v[5] = a.y;
        a = unpack_h2(d0.w); v[6] = a.x; v[7] = a.y;
        a = unpack_h2(d1.x); v[8] = a.x; v[9] = a.y;
        a = unpack_h2(d1.y); v[10] = a.x; v[11] = a.y;
        a = unpack_h2(d1.z); v[12] = a.x; v[13] = a.y;
        a = unpack_h2(d1.w); v[14] = a.x; v[15] = a.y;
    }
    float m = v[0];
#pragma unroll
    for (int j = 1; j < 16; j++) m = fmaxf(m, v[j]);
    red[t] = m;
    __syncthreads();
    for (int o = 128; o > 0; o >>= 1) {
        if (t < o) red[t] = fmaxf(red[t], red[t + o]);
        __syncthreads();
    }
    const float M = red[0];
    __syncthreads();
    float s = 0.f;
#pragma unroll
    for (int j = 0; j < 16; j++) { v[j] = __expf(v[j] - M); s += v[j]; }
    red[t] = s;
    __syncthreads();
    for (int o = 128; o > 0; o >>= 1) {
        if (t < o) red[t] += red[t + o];
        __syncthreads();
    }
    const float inv = 1.0f / red[0];
    d0.x = cvtf16x2(v[1] * inv, v[0] * inv);
    d0.y = cvtf16x2(v[3] * inv, v[2] * inv);
    d0.z = cvtf16x2(v[5] * inv, v[4] * inv);
    d0.w = cvtf16x2(v[7] * inv, v[6] * inv);
    d1.x = cvtf16x2(v[9] * inv, v[8] * inv);
    d1.y = cvtf16x2(v[11] * inv, v[10] * inv);
    d1.z = cvtf16x2(v[13] * inv, v[12] * inv);
    d1.w = cvtf16x2(v[15] * inv, v[14] * inv);
    p[t] = d0;
    p[t + 256] = d1;
}

/* ================== GroupNorm -> fp16 seq [s][c] ================== */
__global__ __launch_bounds__(256) void gn_kernel(
    const float* __restrict__ x,
    const float* __restrict__ gamma,
    const float* __restrict__ beta)
{
    __shared__ float rs[256], rss[256];
    __shared__ float tile[16 * 257];
    __shared__ float sc[16], sh[16];
    const int g = blockIdx.x, n = g >> 5, grp = g & 31;
    const float* xp = x + ((size_t)n * CCH + (size_t)grp * CPG) * HW;
    uint32_t* oh = g_s + (size_t)n * HWC2;
    const int NE = CPG * HW;

    float s = 0.f, ss = 0.f;
    for (int i = threadIdx.x; i < NE; i += 256) {
        float v = xp[i];
        s += v; ss += v * v;
    }
    rs[threadIdx.x] = s; rss[threadIdx.x] = ss;
    __syncthreads();
    for (int o = 128; o > 0; o >>= 1) {
        if (threadIdx.x < o) {
            rs[threadIdx.x] += rs[threadIdx.x + o];
            rss[threadIdx.x] += rss[threadIdx.x + o];
        }
        __syncthreads();
    }
    const float mean = rs[0] * (1.0f / NE);
    const float var  = rss[0] * (1.0f / NE) - mean * mean;
    const float rstd = rsqrtf(var + 1e-5f);
    if (threadIdx.x < 16) {
        int ch = grp * 16 + threadIdx.x;
        float gm = gamma[ch];
        sc[threadIdx.x] = rstd * gm;
        sh[threadIdx.x] = beta[ch] - mean * rstd * gm;
    }
    __syncthreads();

    for (int s0 = 0; s0 < HW; s0 += 256) {
#pragma unroll
        for (int ch = 0; ch < 16; ch++)
            tile[ch * 257 + threadIdx.x] = xp[(size_t)ch * HW + s0 + threadIdx.x] * sc[ch] + sh[ch];
        __syncthreads();
        size_t rowb = (size_t)(s0 + threadIdx.x) * 256 + grp * 8;
#pragma unroll
        for (int c4 = 0; c4 < 4; c4++) {
            float v0 = tile[(c4 * 4 + 0) * 257 + threadIdx.x];
            float v1 = tile[(c4 * 4 + 1) * 257 + threadIdx.x];
            float v2 = tile[(c4 * 4 + 2) * 257 + threadIdx.x];
            float v3 = tile[(c4 * 4 + 3) * 257 + threadIdx.x];
            oh[rowb + c4 * 2]     = cvtf16x2(v1, v0);
            oh[rowb + c4 * 2 + 1] = cvtf16x2(v3, v2);
        }
        __syncthreads();
    }
}

/* ================== round weights to fp16 ================== */
__global__ __launch_bounds__(256) void round_w(
    const float* __restrict__ src, uint32_t* __restrict__ dst, int npairs)
{
    int i = blockIdx.x * 256 + threadIdx.x;
    if (i < npairs) {
        float2 v = *(const float2*)&src[2 * i];
        dst[i] = cvtf16x2(v.y, v.x);
    }
}

/* ================== launch ================== */
extern "C" void kernel_launch(void* const* d_in, const int* in_sizes, int n_in,
                              void* d_out, int out_size)
{
    const float* x     = (const float*)d_in[0];
    const float* gns   = (const float*)d_in[1];
    const float* gnb   = (const float*)d_in[2];
    const float* w_in  = (const float*)d_in[3];
    const float* b_in  = (const float*)d_in[4];
    const float* w_out = (const float*)d_in[5];
    const float* b_out = (const float*)d_in[6];
    float* out = (float*)d_out;

    uint32_t *sp, *wi, *wo, *qq, *kk, *vv, *pp, *at;
    cudaGetSymbolAddress((void**)&sp, g_s);
    cudaGetSymbolAddress((void**)&wi, g_wi);
    cudaGetSymbolAddress((void**)&wo, g_wo);
    cudaGetSymbolAddress((void**)&qq, g_q);
    cudaGetSymbolAddress((void**)&kk, g_k);
    cudaGetSymbolAddress((void**)&vv, g_v);
    cudaGetSymbolAddress((void**)&pp, g_p);
    cudaGetSymbolAddress((void**)&at, g_at);

    const int SM_NN = 3 * (2 * ASZ);          /* 61440 */
    const int SM_PV = 3 * (ASZ + BSZT);       /* 56832 */
    const int SM_M3 = 66048;                  /* proj epilogue staging */

    cudaFuncSetAttribute(gemm_f16<0, false>, cudaFuncAttributeMaxDynamicSharedMemorySize, SM_NN);
    cudaFuncSetAttribute(gemm_f16<1, false>, cudaFuncAttributeMaxDynamicSharedMemorySize, SM_NN);
    cudaFuncSetAttribute(gemm_f16<2, true >, cudaFuncAttributeMaxDynamicSharedMemorySize, SM_PV);
    cudaFuncSetAttribute(gemm_f16<3, false>, cudaFuncAttributeMaxDynamicSharedMemorySize, SM_M3);

    gn_kernel<<<NB * NGRP, 256>>>(x, gns, gnb);
    round_w<<<(D3 * CCH / 2 + 255) / 256, 256>>>(w_in, wi, D3 * CCH / 2);
    round_w<<<(CCH * CCH / 2 + 255) / 256, 256>>>(w_out, wo, CCH * CCH / 2);

    /* QKV: [s][d] = seq . w_in^T + b_in, routed to q/k/v */
    gemm_f16<0, false><<<dim3(D3 / BN, HW / BM, NB), 256, SM_NN>>>(
        sp, wi, qq, kk, vv, b_in, nullptr,
        CCH, CCH * 2, CCH * 2, 256, HWC2, 0, HWC2);

    /* scores: [s][t] = scale * q . k^T -> fp16 */
    gemm_f16<1, false><<<dim3(SEQ / BN, SEQ / BM, NB), 256, SM_NN>>>(
        qq, kk, pp, nullptr, nullptr, nullptr, nullptr,
        CCH, CCH * 2, CCH * 2, 2048, HWC2, HWC2, (size_t)SEQ * SEQ / 2);

    /* softmax in place */
    softmax_f16<<<NB * SEQ, 256>>>();

    /* att: [s][c] = P . V (V [t][c] via ldmatrix.trans) */
    gemm_f16<2, true><<<dim3(CCH / BN, SEQ / BM, NB), 256, SM_PV>>>(
        pp, vv, at, nullptr, nullptr, nullptr, nullptr,
        SEQ, SEQ * 2, CCH * 2, 256, (size_t)SEQ * SEQ / 2, HWC2, HWC2);

    /* proj + bias + residual -> d_out */
    gemm_f16<3, false><<<dim3(CCH / BN, HW / BM, NB), 256, SM_M3>>>(
        at, wo, out, nullptr, nullptr, b_out, x,
        CCH, CCH * 2, CCH * 2, HW, HWC2, 0, (size_t)CCH * HW);
}